// round 8
// baseline (speedup 1.0000x reference)
#include <cuda_runtime.h>
#include <math.h>

#define NB   64
#define IMG  384
#define CIN  3
#define PS   16
#define DM   96
#define DS   16
#define DI   96
#define HP   24
#define NT   576
#define NR   (NB*NT)          // 36864 token rows
#define NPIX (NB*CIN*IMG*IMG) // 28311552

// ---------------- scratch (device globals; no allocs allowed) ----------------
static __device__ float  g_xl[NPIX];        // preprocessed image, PATCH-MAJOR [gp][768]
static __device__ float  g_WpeT[768*96];    // transposed patch weights [k][d]
static __device__ float  g_tokens[NR*DM];
static __device__ float  g_vis[NR];
static __device__ float  g_gate[NR*DM];
static __device__ float  g_xin[NR*DI];      // pre-conv x branch
static __device__ float  g_zg[NR*DI];       // silu(z)*vis
static __device__ float  g_yg[NR*DI];

__device__ __forceinline__ float sigm_(float x){ return 1.f/(1.f+__expf(-x)); }
__device__ __forceinline__ float silu_(float x){ return x/(1.f+__expf(-x)); }
__device__ __forceinline__ float softplus_(float x){ return (x>20.f)? x : __logf(1.f+__expf(x)); }

// ---- packed fp32x2 helpers (Blackwell FFMA2 path, PTX-only) ----
typedef unsigned long long u64;
__device__ __forceinline__ void ffma2(u64 &d, u64 a, u64 b){
    asm("fma.rn.f32x2 %0, %1, %2, %3;" : "=l"(d) : "l"(a), "l"(b), "l"(d));
}
__device__ __forceinline__ u64 pack2(float x, float y){
    u64 r;
    asm("mov.b64 %0, {%1, %2};" : "=l"(r) : "r"(__float_as_uint(x)), "r"(__float_as_uint(y)));
    return r;
}
__device__ __forceinline__ float2 unpack2(u64 v){
    unsigned lo, hi;
    asm("mov.b64 {%0, %1}, %2;" : "=r"(lo), "=r"(hi) : "l"(v));
    return make_float2(__uint_as_float(lo), __uint_as_float(hi));
}

// ---------------- 0) transpose W_pe once ----------------
__global__ void k_wt(const float* __restrict__ Wpe){
    int idx = blockIdx.x*blockDim.x + threadIdx.x;
    if (idx < 768*96){
        int k = idx/96, d = idx%96;
        g_WpeT[idx] = Wpe[d*768 + k];
    }
}

// ---------------- 1) fused 5x5 box blur + log contrast (smem tiles) ----------------
__global__ void k_blur(const float* __restrict__ x){
    __shared__ float in_s[36][37];
    __shared__ float hs[36][33];
    int tid = threadIdx.x;                   // 256
    int p = blockIdx.x / 144;                // plane = b*3 + c
    int t = blockIdx.x % 144;
    int y0 = (t/12)*32, x0 = (t%12)*32;
    const float* xp = x + (size_t)p*IMG*IMG;

    for (int idx=tid; idx<36*36; idx+=256){
        int r = idx/36, cc = idx%36;
        int yy = y0-2+r, xx = x0-2+cc;
        in_s[r][cc] = (yy>=0 && yy<IMG && xx>=0 && xx<IMG) ? xp[yy*IMG+xx] : 0.f;
    }
    __syncthreads();
    for (int idx=tid; idx<36*32; idx+=256){
        int r = idx/32, j = idx%32;
        hs[r][j] = in_s[r][j]+in_s[r][j+1]+in_s[r][j+2]+in_s[r][j+3]+in_s[r][j+4];
    }
    __syncthreads();
    int b = p/3, c = p%3;
    for (int idx=tid; idx<32*32; idx+=256){
        int r = idx/32, j = idx%32;
        float bl = (hs[r][j]+hs[r+1][j]+hs[r+2][j]+hs[r+3][j]+hs[r+4][j])*(1.f/25.f);
        float xv = in_s[r+2][j+2];
        float v  = __logf(1.f + fmaxf(xv,0.f)) - __logf(1.f + fmaxf(bl,0.f));
        int yy = y0+r, xx = x0+j;
        int gp  = b*NT + (yy>>4)*HP + (xx>>4);
        int col = c*256 + (yy&15)*16 + (xx&15);
        g_xl[gp*768 + col] = v;
    }
}

// ---------------- 2) patch embed GEMM (proven): [36864 x 768] @ [768 x 96] ----------------
__global__ void k_patch(const float* __restrict__ bpe){
    __shared__ __align__(16) float As[64][64];
    __shared__ __align__(16) float Bs[64][96];
    int tid = threadIdx.x;
    int tx = tid & 15, ty = tid >> 4;        // tx 0..15, ty 0..7
    int rowbase = blockIdx.x * 64;
    int tx6 = tx*6;

    u64 acc[8][3];
    #pragma unroll
    for (int i=0;i<8;i++){ acc[i][0]=0ull; acc[i][1]=0ull; acc[i][2]=0ull; }

    const float4* Xg = reinterpret_cast<const float4*>(g_xl);
    const float4* Wg = reinterpret_cast<const float4*>(g_WpeT);
    float4* As4 = reinterpret_cast<float4*>(&As[0][0]);
    float4* Bs4 = reinterpret_cast<float4*>(&Bs[0][0]);

    for (int kc=0; kc<12; kc++){
        #pragma unroll
        for (int r=0;r<8;r++){
            int idx = tid + 128*r;           // < 1024
            int row = idx >> 4, c4 = idx & 15;
            As4[idx] = Xg[(rowbase+row)*192 + kc*16 + c4];
        }
        #pragma unroll
        for (int r=0;r<12;r++){
            int idx = tid + 128*r;           // < 1536
            int kk = idx/24, c4 = idx%24;
            Bs4[idx] = Wg[(kc*64+kk)*24 + c4];
        }
        __syncthreads();
        #pragma unroll 8
        for (int kk=0;kk<64;kk++){
            const u64* bp = reinterpret_cast<const u64*>(&Bs[kk][tx6]);
            u64 b0 = bp[0], b1 = bp[1], b2 = bp[2];
            #pragma unroll
            for (int i=0;i<8;i++){
                float a = As[ty + 8*i][kk];
                u64 ap = pack2(a, a);
                ffma2(acc[i][0], ap, b0);
                ffma2(acc[i][1], ap, b1);
                ffma2(acc[i][2], ap, b2);
            }
        }
        __syncthreads();
    }
    #pragma unroll
    for (int i=0;i<8;i++){
        int row = rowbase + ty + 8*i;
        #pragma unroll
        for (int j=0;j<3;j++){
            float2 v = unpack2(acc[i][j]);
            int c = tx6 + 2*j;
            g_tokens[row*DM + c]   = v.x + bpe[c];
            g_tokens[row*DM + c+1] = v.y + bpe[c+1];
        }
    }
}

// ---------------- shared GEMM building blocks (proven R2/R7 mainloop) ----------------
template<int WSTRIDE>
__device__ __forceinline__ void gemm96(float (*As)[96], float (*Bs)[96],
                                       const float* __restrict__ W, int cb,
                                       int tid, int tx6, int ty, u64 acc[8][3]){
    float4* Bs4 = reinterpret_cast<float4*>(&Bs[0][0]);
    #pragma unroll
    for (int i=0;i<8;i++){ acc[i][0]=0ull; acc[i][1]=0ull; acc[i][2]=0ull; }
    for (int kc=0;kc<3;kc++){
        __syncthreads();
        #pragma unroll
        for (int r=0;r<6;r++){
            int idx = tid + 128*r;            // < 768
            int kk = idx/24, c4 = idx%24;
            Bs4[idx] = *reinterpret_cast<const float4*>(W + (kc*32+kk)*WSTRIDE + cb + c4*4);
        }
        __syncthreads();
        #pragma unroll 8
        for (int kk=0;kk<32;kk++){
            const u64* bp = reinterpret_cast<const u64*>(&Bs[kk][tx6]);
            u64 b0 = bp[0], b1 = bp[1], b2 = bp[2];
            int kidx = kc*32 + kk;
            #pragma unroll
            for (int i=0;i<8;i++){
                float a = As[ty + 8*i][kidx];
                u64 ap = pack2(a, a);
                ffma2(acc[i][0], ap, b0);
                ffma2(acc[i][1], ap, b1);
                ffma2(acc[i][2], ap, b2);
            }
        }
    }
}

// plain LN over 64 rows in As (shfl version, proven)
__device__ __forceinline__ void ln64(float (*As)[96],
                                     const float* __restrict__ g,
                                     const float* __restrict__ bta, int tid){
    int warp = tid >> 5, lane = tid & 31;
    for (int rr=0; rr<16; rr++){
        int row = warp*16 + rr;
        float v0 = As[row][lane], v1 = As[row][lane+32], v2 = As[row][lane+64];
        float s = v0+v1+v2;
        #pragma unroll
        for (int o=16;o;o>>=1) s += __shfl_xor_sync(0xffffffffu, s, o);
        float m = s*(1.f/96.f);
        float d0=v0-m, d1=v1-m, d2=v2-m;
        float q = d0*d0 + d1*d1 + d2*d2;
        #pragma unroll
        for (int o=16;o;o>>=1) q += __shfl_xor_sync(0xffffffffu, q, o);
        float rs = rsqrtf(q*(1.f/96.f) + 1e-5f);
        As[row][lane]    = d0*rs*g[lane]    + bta[lane];
        As[row][lane+32] = d1*rs*g[lane+32] + bta[lane+32];
        As[row][lane+64] = d2*rs*g[lane+64] + bta[lane+64];
    }
}

// W_in epilogue: write xin (half 0) / zg (half 1)
__device__ __forceinline__ void win_epi(u64 acc[8][3], int rowbase, int ty, int tx6,
                                        int half){
    #pragma unroll
    for (int i=0;i<8;i++){
        int row = rowbase + ty + 8*i;
        float visr = (half==1) ? g_vis[row] : 0.f;
        #pragma unroll
        for (int j=0;j<3;j++){
            float2 v = unpack2(acc[i][j]);
            int c = tx6 + 2*j;
            if (half == 0){
                g_xin[row*96 + c]   = v.x;
                g_xin[row*96 + c+1] = v.y;
            } else {
                g_zg[row*96 + c]   = silu_(v.x)*visr;
                g_zg[row*96 + c+1] = silu_(v.y)*visr;
            }
        }
    }
}

// ---------------- 3a) fused MODE0 + MODE1: vis, LN(dn)->tokens, gate, LN(ln), W_in ----------------
__global__ void k_rg01(const float* __restrict__ W_gate, const float* __restrict__ W_in,
                       const float* __restrict__ dn_g, const float* __restrict__ dn_b,
                       const float* __restrict__ ln_g, const float* __restrict__ ln_b,
                       const float* __restrict__ Wvis, const float* __restrict__ bvis,
                       const float* __restrict__ bgate){
    __shared__ __align__(16) float As[64][96];
    __shared__ __align__(16) float Bs[32][96];
    int tid = threadIdx.x;
    int tx = tid & 15, ty = tid >> 4;
    int rowbase = blockIdx.x * 64;
    int tx6 = tx*6;

    const float4* Ag = reinterpret_cast<const float4*>(g_tokens + rowbase*96);
    float4* As4 = reinterpret_cast<float4*>(&As[0][0]);
    #pragma unroll
    for (int r=0;r<12;r++) As4[tid + 128*r] = Ag[tid + 128*r];
    __syncthreads();

    // LN(dn) with vis; write tokens back
    {
        int warp = tid >> 5, lane = tid & 31;
        for (int rr=0; rr<16; rr++){
            int row = warp*16 + rr;
            float v0 = As[row][lane], v1 = As[row][lane+32], v2 = As[row][lane+64];
            float s = v0+v1+v2;
            #pragma unroll
            for (int o=16;o;o>>=1) s += __shfl_xor_sync(0xffffffffu, s, o);
            float m = s*(1.f/96.f);
            float d0=v0-m, d1=v1-m, d2=v2-m;
            float q = d0*d0 + d1*d1 + d2*d2;
            #pragma unroll
            for (int o=16;o;o>>=1) q += __shfl_xor_sync(0xffffffffu, q, o);
            float rs = rsqrtf(q*(1.f/96.f) + 1e-5f);
            float vd = v0*Wvis[lane] + v1*Wvis[lane+32] + v2*Wvis[lane+64];
            #pragma unroll
            for (int o=16;o;o>>=1) vd += __shfl_xor_sync(0xffffffffu, vd, o);
            if (lane==0) g_vis[rowbase+row] = sigm_(vd + bvis[0]);
            float n0 = d0*rs*dn_g[lane]    + dn_b[lane];
            float n1 = d1*rs*dn_g[lane+32] + dn_b[lane+32];
            float n2 = d2*rs*dn_g[lane+64] + dn_b[lane+64];
            As[row][lane]=n0; As[row][lane+32]=n1; As[row][lane+64]=n2;
            float* tp = g_tokens + (rowbase+row)*96;
            tp[lane]=n0; tp[lane+32]=n1; tp[lane+64]=n2;
        }
    }

    u64 acc[8][3];
    // gate = sigmoid(As @ W_gate + b_gate)
    gemm96<96>(As, Bs, W_gate, 0, tid, tx6, ty, acc);
    #pragma unroll
    for (int i=0;i<8;i++){
        int row = rowbase + ty + 8*i;
        #pragma unroll
        for (int j=0;j<3;j++){
            float2 v = unpack2(acc[i][j]);
            int c = tx6 + 2*j;
            g_gate[row*96 + c]   = sigm_(v.x + bgate[c]);
            g_gate[row*96 + c+1] = sigm_(v.y + bgate[c+1]);
        }
    }
    __syncthreads();

    // LN(ln), then W_in both halves
    ln64(As, ln_g, ln_b, tid);
    gemm96<192>(As, Bs, W_in, 0, tid, tx6, ty, acc);
    win_epi(acc, rowbase, ty, tx6, 0);
    gemm96<192>(As, Bs, W_in, 96, tid, tx6, ty, acc);
    win_epi(acc, rowbase, ty, tx6, 1);
}

// ---------------- 3b) fused MODE2 (+ next-rep MODE1): W_out, residual, LN(ln), W_in ----------------
template<bool DO_IN>
__global__ void k_rg21(const float* __restrict__ W_out, const float* __restrict__ W_in,
                       const float* __restrict__ ln_g, const float* __restrict__ ln_b){
    __shared__ __align__(16) float As[64][96];
    __shared__ __align__(16) float Bs[32][96];
    int tid = threadIdx.x;
    int tx = tid & 15, ty = tid >> 4;
    int rowbase = blockIdx.x * 64;
    int tx6 = tx*6;

    const float4* Ag = reinterpret_cast<const float4*>(g_yg + rowbase*96);
    float4* As4 = reinterpret_cast<float4*>(&As[0][0]);
    #pragma unroll
    for (int r=0;r<12;r++) As4[tid + 128*r] = Ag[tid + 128*r];

    u64 acc[8][3];
    gemm96<96>(As, Bs, W_out, 0, tid, tx6, ty, acc);
    __syncthreads();  // everyone done reading As before overwrite
    #pragma unroll
    for (int i=0;i<8;i++){
        int row = rowbase + ty + 8*i;
        int rl  = ty + 8*i;
        #pragma unroll
        for (int j=0;j<3;j++){
            float2 v = unpack2(acc[i][j]);
            int c = tx6 + 2*j;
            float t0 = g_tokens[row*96 + c]   + v.x * g_gate[row*96 + c];
            float t1 = g_tokens[row*96 + c+1] + v.y * g_gate[row*96 + c+1];
            g_tokens[row*96 + c]   = t0;
            g_tokens[row*96 + c+1] = t1;
            As[rl][c]   = t0;
            As[rl][c+1] = t1;
        }
    }

    if (DO_IN){
        __syncthreads();
        ln64(As, ln_g, ln_b, tid);
        gemm96<192>(As, Bs, W_in, 0, tid, tx6, ty, acc);
        win_epi(acc, rowbase, ty, tx6, 0);
        gemm96<192>(As, Bs, W_in, 96, tid, tx6, ty, acc);
        win_epi(acc, rowbase, ty, tx6, 1);
    }
}

// ---------------- 4) fused conv+silu + proj + dt + scan (persistent per b,d-half) ----------------
__global__ void __launch_bounds__(384) k_css(const float* __restrict__ cw,
                    const float* __restrict__ Wx, const float* __restrict__ Wdt,
                    const float* __restrict__ bdt, const float* __restrict__ Dp,
                    const float* __restrict__ Alog){
    __shared__ float xs_s[32*97];
    __shared__ float Wxs[96*38];
    __shared__ float prs[32*9];
    __shared__ float bcs[32*34];
    __shared__ float dts[32*48];
    __shared__ float cws[288];
    __shared__ float wdts[6*48];
    __shared__ float bdts[48];
    int tid = threadIdx.x;                   // 384
    int b   = blockIdx.x >> 1;
    int dh  = blockIdx.x & 1;
    int dbase = dh*48;
    int rb  = b*NT;

    for (int idx=tid; idx<96*38; idx+=384) Wxs[idx] = Wx[idx];
    for (int idx=tid; idx<6*48;  idx+=384){ int r=idx/48, j=idx%48; wdts[idx] = Wdt[r*96 + dbase + j]; }
    if (tid < 96){
        cws[tid] = cw[tid*3+0]; cws[96+tid] = cw[tid*3+1]; cws[192+tid] = cw[tid*3+2];
    }
    if (tid < 48) bdts[tid] = bdt[dbase + tid];

    int w = tid>>5, lane = tid&31, g = lane>>3, sl = lane&7;
    int dl = w*4 + g;                        // 0..47
    int d  = dbase + dl;
    int s0 = 2*sl;
    float A0 = -__expf(Alog[d*DS + s0]);
    float A1 = -__expf(Alog[d*DS + s0 + 1]);
    float Dd = Dp[d];
    float h0 = 0.f, h1 = 0.f;
    __syncthreads();

    for (int c=0;c<18;c++){
        int t0 = c*32;
        // conv + silu (all 96 d)
        for (int idx=tid; idx<32*96; idx+=384){
            int l = idx/96, dd = idx%96;
            const float* xp = g_xin + (rb + t0 + l)*96 + dd;
            float v = xp[0]*cws[192+dd];
            if (t0+l >= 1) v = fmaf(xp[-96],  cws[96+dd], v);
            if (t0+l >= 2) v = fmaf(xp[-192], cws[dd],    v);
            xs_s[l*97 + dd] = silu_(v);
        }
        __syncthreads();
        // proj: [32 x 96] @ [96 x 38] token-pair FFMA2
        {
            int tp = tid & 15;               // token pair 0..15
            int jg = tid >> 4;               // 0..23
            int j1 = jg + 24;
            bool do1 = (j1 < 38);
            u64 a0 = 0ull, a1 = 0ull;
            const float* x0 = &xs_s[(2*tp)*97];
            const float* x1 = x0 + 97;
            #pragma unroll 4
            for (int k=0;k<96;k++){
                u64 ap = pack2(x0[k], x1[k]);
                float w0 = Wxs[k*38 + jg];
                ffma2(a0, ap, pack2(w0, w0));
                if (do1){
                    float w1 = Wxs[k*38 + j1];
                    ffma2(a1, ap, pack2(w1, w1));
                }
            }
            float2 v0 = unpack2(a0);
            if (jg < 6){
                prs[(2*tp)*9 + jg]   = v0.x;
                prs[(2*tp+1)*9 + jg] = v0.y;
            } else {
                bcs[(2*tp)*34 + jg-6]   = v0.x;
                bcs[(2*tp+1)*34 + jg-6] = v0.y;
            }
            if (do1){
                float2 v1 = unpack2(a1);
                bcs[(2*tp)*34 + j1-6]   = v1.x;
                bcs[(2*tp+1)*34 + j1-6] = v1.y;
            }
        }
        __syncthreads();
        // dt = softplus(dt_raw @ W_dt + b_dt), my 48 d
        for (int idx=tid; idx<32*48; idx+=384){
            int l = idx/48, j = idx%48;
            float a = bdts[j];
            #pragma unroll
            for (int r=0;r<6;r++) a = fmaf(prs[l*9+r], wdts[r*48+j], a);
            dts[idx] = softplus_(a);
        }
        __syncthreads();
        // scan 32 steps
        #pragma unroll 4
        for (int l=0;l<32;l++){
            float dt = dts[l*48 + dl];
            float xs = xs_s[l*97 + d];
            float2 Bv = *reinterpret_cast<const float2*>(&bcs[l*34 + s0]);
            float2 Cv = *reinterpret_cast<const float2*>(&bcs[l*34 + 16 + s0]);
            float u = dt*xs;
            h0 = fmaf(__expf(dt*A0), h0, u*Bv.x);
            h1 = fmaf(__expf(dt*A1), h1, u*Bv.y);
            float yp = fmaf(h1, Cv.y, h0*Cv.x);
            yp += __shfl_xor_sync(0xffffffffu, yp, 1);
            yp += __shfl_xor_sync(0xffffffffu, yp, 2);
            yp += __shfl_xor_sync(0xffffffffu, yp, 4);
            if (sl == 0){
                float zg = g_zg[(rb + t0 + l)*96 + d];
                g_yg[(rb + t0 + l)*96 + d] = fmaf(Dd, xs, yp) * zg;
            }
        }
        __syncthreads();
    }
}

// ---------------- 5) heads: depthwise 3x3 + BN + silu + three matvecs ----------------
__global__ void k_final(const float* __restrict__ hd,
                        const float* __restrict__ bng, const float* __restrict__ bnb,
                        const float* __restrict__ bnm, const float* __restrict__ bnv,
                        const float* __restrict__ Wheat, const float* __restrict__ bheat,
                        const float* __restrict__ Woff,  const float* __restrict__ boff,
                        const float* __restrict__ Wsize, const float* __restrict__ bsize,
                        float* __restrict__ out){
    __shared__ float fr[3][HP][97];
    __shared__ float gs[HP][97];
    int tid = threadIdx.x;
    int b = blockIdx.x / HP;
    int h = blockIdx.x % HP;

    for (int idx=tid; idx<3*HP*96; idx+=128){
        int r = idx/(HP*96);
        int rem = idx - r*HP*96;
        int wq = rem/96, d = rem%96;
        int hh = h - 1 + r;
        fr[r][wq][d] = (hh>=0 && hh<HP) ? g_tokens[(b*NT + hh*HP + wq)*DM + d] : 0.f;
    }
    __syncthreads();

    for (int idx=tid; idx<HP*96; idx+=128){
        int wq = idx/96, d = idx%96;
        float a = 0.f;
        #pragma unroll
        for (int i=0;i<3;i++)
            #pragma unroll
            for (int j=0;j<3;j++){
                int ww = wq - 1 + j;
                if (ww>=0 && ww<HP) a = fmaf(fr[i][ww][d], hd[d*9 + i*3 + j], a);
            }
        a = (a - bnm[d]) * rsqrtf(bnv[d] + 1e-5f);
        gs[wq][d] = silu_(a*bng[d] + bnb[d]);
    }
    __syncthreads();

    const int HEAT_OFF = 0;
    const int OFF_OFF  = NB*5*NT;
    const int SIZE_OFF = OFF_OFF + NB*2*NT;
    for (int idx=tid; idx<HP*9; idx+=128){
        int wq = idx/9, o = idx%9;
        if (o < 5){
            float a = bheat[o];
            #pragma unroll 8
            for (int d=0; d<96; d++) a = fmaf(gs[wq][d], Wheat[o*96+d], a);
            out[HEAT_OFF + ((b*5+o)*HP + h)*HP + wq] = a;
        } else if (o < 7){
            int oo = o-5;
            float a = boff[oo];
            #pragma unroll 8
            for (int d=0; d<96; d++) a = fmaf(fr[1][wq][d], Woff[oo*96+d], a);
            out[OFF_OFF + ((b*2+oo)*HP + h)*HP + wq] = a;
        } else {
            int oo = o-7;
            float a = bsize[oo];
            #pragma unroll 8
            for (int d=0; d<96; d++) a = fmaf(fr[1][wq][d], Wsize[oo*96+d], a);
            out[SIZE_OFF + ((b*2+oo)*HP + h)*HP + wq] = a;
        }
    }
}

// ---------------- launch ----------------
extern "C" void kernel_launch(void* const* d_in, const int* in_sizes, int n_in,
                              void* d_out, int out_size){
    const float* x      = (const float*)d_in[0];
    const float* W_pe   = (const float*)d_in[1];
    const float* b_pe   = (const float*)d_in[2];
    const float* W_vis  = (const float*)d_in[3];
    const float* b_vis  = (const float*)d_in[4];
    const float* dn_g   = (const float*)d_in[5];
    const float* dn_b   = (const float*)d_in[6];
    const float* W_gate = (const float*)d_in[7];
    const float* b_gate = (const float*)d_in[8];
    const float* ln_g   = (const float*)d_in[9];
    const float* ln_b   = (const float*)d_in[10];
    const float* W_in   = (const float*)d_in[11];
    const float* conv_w = (const float*)d_in[12];
    const float* W_xprj = (const float*)d_in[13];
    const float* W_dt   = (const float*)d_in[14];
    const float* b_dt   = (const float*)d_in[15];
    const float* A_log  = (const float*)d_in[16];
    const float* Dp     = (const float*)d_in[17];
    const float* W_out  = (const float*)d_in[18];
    const float* hd_dw  = (const float*)d_in[19];
    const float* bn_g   = (const float*)d_in[20];
    const float* bn_b   = (const float*)d_in[21];
    const float* bn_m   = (const float*)d_in[22];
    const float* bn_v   = (const float*)d_in[23];
    const float* W_heat = (const float*)d_in[24];
    const float* b_heat = (const float*)d_in[25];
    const float* W_off  = (const float*)d_in[26];
    const float* b_off  = (const float*)d_in[27];
    const float* W_size = (const float*)d_in[28];
    const float* b_size = (const float*)d_in[29];
    float* out = (float*)d_out;

    k_wt<<<(768*96+255)/256, 256>>>(W_pe);
    k_blur<<<192*144, 256>>>(x);
    k_patch<<<NR/64, 128>>>(b_pe);

    // MODE0 + first MODE1
    k_rg01<<<NR/64, 128>>>(W_gate, W_in, dn_g, dn_b, ln_g, ln_b, W_vis, b_vis, b_gate);

    for (int rep=0; rep<3; rep++){
        k_css<<<NB*2, 384>>>(conv_w, W_xprj, W_dt, b_dt, Dp, A_log);
        k_rg21<true><<<NR/64, 128>>>(W_out, W_in, ln_g, ln_b);
    }
    k_css<<<NB*2, 384>>>(conv_w, W_xprj, W_dt, b_dt, Dp, A_log);
    k_rg21<false><<<NR/64, 128>>>(W_out, W_in, ln_g, ln_b);

    k_final<<<NB*HP, 128>>>(hd_dw, bn_g, bn_b, bn_m, bn_v,
                            W_heat, b_heat, W_off, b_off, W_size, b_size, out);
}

// round 9
// speedup vs baseline: 1.1508x; 1.1508x over previous
#include <cuda_runtime.h>
#include <math.h>

#define NB   64
#define IMG  384
#define CIN  3
#define PS   16
#define DM   96
#define DS   16
#define DI   96
#define HP   24
#define NT   576
#define NR   (NB*NT)          // 36864 token rows
#define NPIX (NB*CIN*IMG*IMG) // 28311552

// ---------------- scratch (device globals; no allocs allowed) ----------------
static __device__ float  g_xl[NPIX];        // preprocessed image, PATCH-MAJOR [gp][768]
static __device__ float  g_WpeT[768*96];    // transposed patch weights [k][d]
static __device__ float  g_tokens[NR*DM];
static __device__ float  g_vis[NR];
static __device__ float  g_gate[NR*DM];
static __device__ float  g_xin[NR*DI];      // pre-conv x branch
static __device__ float  g_zg[NR*DI];       // silu(z)*vis
static __device__ float  g_bc[NR*32];       // B(16) | C(16)
static __device__ float4 g_meta[NR*DI];     // {dt, dt*xs, D*xs*zg, zg}
static __device__ float  g_yg[NR*DI];

__device__ __forceinline__ float sigm_(float x){ return 1.f/(1.f+__expf(-x)); }
__device__ __forceinline__ float silu_(float x){ return x/(1.f+__expf(-x)); }
__device__ __forceinline__ float softplus_(float x){ return (x>20.f)? x : __logf(1.f+__expf(x)); }

// ---- packed fp32x2 helpers (Blackwell FFMA2 path, PTX-only) ----
typedef unsigned long long u64;
__device__ __forceinline__ void ffma2(u64 &d, u64 a, u64 b){
    asm("fma.rn.f32x2 %0, %1, %2, %3;" : "=l"(d) : "l"(a), "l"(b), "l"(d));
}
__device__ __forceinline__ u64 pack2(float x, float y){
    u64 r;
    asm("mov.b64 %0, {%1, %2};" : "=l"(r) : "r"(__float_as_uint(x)), "r"(__float_as_uint(y)));
    return r;
}
__device__ __forceinline__ float2 unpack2(u64 v){
    unsigned lo, hi;
    asm("mov.b64 {%0, %1}, %2;" : "=r"(lo), "=r"(hi) : "l"(v));
    return make_float2(__uint_as_float(lo), __uint_as_float(hi));
}

// ---------------- 0) transpose W_pe once ----------------
__global__ void k_wt(const float* __restrict__ Wpe){
    int idx = blockIdx.x*blockDim.x + threadIdx.x;
    if (idx < 768*96){
        int k = idx/96, d = idx%96;
        g_WpeT[idx] = Wpe[d*768 + k];
    }
}

// ---------------- 1) fused 5x5 box blur + log contrast (smem tiles) ----------------
__global__ void k_blur(const float* __restrict__ x){
    __shared__ float in_s[36][37];
    __shared__ float hs[36][33];
    int tid = threadIdx.x;                   // 256
    int p = blockIdx.x / 144;                // plane = b*3 + c
    int t = blockIdx.x % 144;
    int y0 = (t/12)*32, x0 = (t%12)*32;
    const float* xp = x + (size_t)p*IMG*IMG;

    for (int idx=tid; idx<36*36; idx+=256){
        int r = idx/36, cc = idx%36;
        int yy = y0-2+r, xx = x0-2+cc;
        in_s[r][cc] = (yy>=0 && yy<IMG && xx>=0 && xx<IMG) ? xp[yy*IMG+xx] : 0.f;
    }
    __syncthreads();
    for (int idx=tid; idx<36*32; idx+=256){
        int r = idx/32, j = idx%32;
        hs[r][j] = in_s[r][j]+in_s[r][j+1]+in_s[r][j+2]+in_s[r][j+3]+in_s[r][j+4];
    }
    __syncthreads();
    int b = p/3, c = p%3;
    for (int idx=tid; idx<32*32; idx+=256){
        int r = idx/32, j = idx%32;
        float bl = (hs[r][j]+hs[r+1][j]+hs[r+2][j]+hs[r+3][j]+hs[r+4][j])*(1.f/25.f);
        float xv = in_s[r+2][j+2];
        float v  = __logf(1.f + fmaxf(xv,0.f)) - __logf(1.f + fmaxf(bl,0.f));
        int yy = y0+r, xx = x0+j;
        int gp  = b*NT + (yy>>4)*HP + (xx>>4);
        int col = c*256 + (yy&15)*16 + (xx&15);
        g_xl[gp*768 + col] = v;
    }
}

// ---------------- 2) patch embed GEMM (proven): [36864 x 768] @ [768 x 96] ----------------
__global__ void k_patch(const float* __restrict__ bpe){
    __shared__ __align__(16) float As[64][64];
    __shared__ __align__(16) float Bs[64][96];
    int tid = threadIdx.x;
    int tx = tid & 15, ty = tid >> 4;        // tx 0..15, ty 0..7
    int rowbase = blockIdx.x * 64;
    int tx6 = tx*6;

    u64 acc[8][3];
    #pragma unroll
    for (int i=0;i<8;i++){ acc[i][0]=0ull; acc[i][1]=0ull; acc[i][2]=0ull; }

    const float4* Xg = reinterpret_cast<const float4*>(g_xl);
    const float4* Wg = reinterpret_cast<const float4*>(g_WpeT);
    float4* As4 = reinterpret_cast<float4*>(&As[0][0]);
    float4* Bs4 = reinterpret_cast<float4*>(&Bs[0][0]);

    for (int kc=0; kc<12; kc++){
        #pragma unroll
        for (int r=0;r<8;r++){
            int idx = tid + 128*r;           // < 1024
            int row = idx >> 4, c4 = idx & 15;
            As4[idx] = Xg[(rowbase+row)*192 + kc*16 + c4];
        }
        #pragma unroll
        for (int r=0;r<12;r++){
            int idx = tid + 128*r;           // < 1536
            int kk = idx/24, c4 = idx%24;
            Bs4[idx] = Wg[(kc*64+kk)*24 + c4];
        }
        __syncthreads();
        #pragma unroll 8
        for (int kk=0;kk<64;kk++){
            const u64* bp = reinterpret_cast<const u64*>(&Bs[kk][tx6]);
            u64 b0 = bp[0], b1 = bp[1], b2 = bp[2];
            #pragma unroll
            for (int i=0;i<8;i++){
                float a = As[ty + 8*i][kk];
                u64 ap = pack2(a, a);
                ffma2(acc[i][0], ap, b0);
                ffma2(acc[i][1], ap, b1);
                ffma2(acc[i][2], ap, b2);
            }
        }
        __syncthreads();
    }
    #pragma unroll
    for (int i=0;i<8;i++){
        int row = rowbase + ty + 8*i;
        #pragma unroll
        for (int j=0;j<3;j++){
            float2 v = unpack2(acc[i][j]);
            int c = tx6 + 2*j;
            g_tokens[row*DM + c]   = v.x + bpe[c];
            g_tokens[row*DM + c+1] = v.y + bpe[c+1];
        }
    }
}

// ---------------- 3) row GEMM with fused LN + epilogues (proven R7) ----------------
template<int MODE>
__global__ void k_rowgemm(const float* __restrict__ W, int wstride,
                          const float* __restrict__ lng, const float* __restrict__ lnb,
                          const float* __restrict__ Wvis, const float* __restrict__ bvis,
                          const float* __restrict__ bgate){
    __shared__ __align__(16) float As[64][96];
    __shared__ __align__(16) float Bs[32][96];
    int tid = threadIdx.x;
    int tx = tid & 15, ty = tid >> 4;
    int rowbase = blockIdx.x * 64;
    int tx6 = tx*6;

    const float* Asrc = (MODE==2) ? g_yg : g_tokens;
    const float4* Ag = reinterpret_cast<const float4*>(Asrc + rowbase*96);
    float4* As4 = reinterpret_cast<float4*>(&As[0][0]);
    float4* Bs4 = reinterpret_cast<float4*>(&Bs[0][0]);
    #pragma unroll
    for (int r=0;r<12;r++) As4[tid + 128*r] = Ag[tid + 128*r];
    __syncthreads();

    if (MODE != 2){
        int warp = tid >> 5, lane = tid & 31;
        for (int rr=0; rr<16; rr++){
            int row = warp*16 + rr;
            float v0 = As[row][lane], v1 = As[row][lane+32], v2 = As[row][lane+64];
            float s = v0+v1+v2;
            #pragma unroll
            for (int o=16;o;o>>=1) s += __shfl_xor_sync(0xffffffffu, s, o);
            float m = s*(1.f/96.f);
            float d0=v0-m, d1=v1-m, d2=v2-m;
            float q = d0*d0 + d1*d1 + d2*d2;
            #pragma unroll
            for (int o=16;o;o>>=1) q += __shfl_xor_sync(0xffffffffu, q, o);
            float rs = rsqrtf(q*(1.f/96.f) + 1e-5f);
            if (MODE == 0){
                float vd = v0*Wvis[lane] + v1*Wvis[lane+32] + v2*Wvis[lane+64];
                #pragma unroll
                for (int o=16;o;o>>=1) vd += __shfl_xor_sync(0xffffffffu, vd, o);
                if (lane==0) g_vis[rowbase+row] = sigm_(vd + bvis[0]);
            }
            float n0 = d0*rs*lng[lane]    + lnb[lane];
            float n1 = d1*rs*lng[lane+32] + lnb[lane+32];
            float n2 = d2*rs*lng[lane+64] + lnb[lane+64];
            As[row][lane]=n0; As[row][lane+32]=n1; As[row][lane+64]=n2;
            if (MODE == 0){
                float* tp = g_tokens + (rowbase+row)*96;
                tp[lane]=n0; tp[lane+32]=n1; tp[lane+64]=n2;
            }
        }
    }

    const int NHALF = (MODE==1) ? 2 : 1;
    for (int half=0; half<NHALF; half++){
        int cb = half*96;

        u64 acc[8][3];
        #pragma unroll
        for (int i=0;i<8;i++){ acc[i][0]=0ull; acc[i][1]=0ull; acc[i][2]=0ull; }

        for (int kc=0;kc<3;kc++){
            __syncthreads();
            #pragma unroll
            for (int r=0;r<6;r++){
                int idx = tid + 128*r;        // < 768
                int kk = idx/24, c4 = idx%24;
                Bs4[idx] = *reinterpret_cast<const float4*>(W + (kc*32+kk)*wstride + cb + c4*4);
            }
            __syncthreads();
            #pragma unroll 8
            for (int kk=0;kk<32;kk++){
                const u64* bp = reinterpret_cast<const u64*>(&Bs[kk][tx6]);
                u64 b0 = bp[0], b1 = bp[1], b2 = bp[2];
                int kidx = kc*32 + kk;
                #pragma unroll
                for (int i=0;i<8;i++){
                    float a = As[ty + 8*i][kidx];
                    u64 ap = pack2(a, a);
                    ffma2(acc[i][0], ap, b0);
                    ffma2(acc[i][1], ap, b1);
                    ffma2(acc[i][2], ap, b2);
                }
            }
        }

        #pragma unroll
        for (int i=0;i<8;i++){
            int row = rowbase + ty + 8*i;
            float visr = 0.f;
            if (MODE == 1 && half == 1) visr = g_vis[row];
            #pragma unroll
            for (int j=0;j<3;j++){
                float2 v = unpack2(acc[i][j]);
                int c = tx6 + 2*j;
                if (MODE == 0){
                    g_gate[row*96 + c]   = sigm_(v.x + bgate[c]);
                    g_gate[row*96 + c+1] = sigm_(v.y + bgate[c+1]);
                } else if (MODE == 1){
                    if (half == 0){
                        g_xin[row*96 + c]   = v.x;
                        g_xin[row*96 + c+1] = v.y;
                    } else {
                        g_zg[row*96 + c]   = silu_(v.x)*visr;
                        g_zg[row*96 + c+1] = silu_(v.y)*visr;
                    }
                } else {
                    g_tokens[row*96 + c]   += v.x * g_gate[row*96 + c];
                    g_tokens[row*96 + c+1] += v.y * g_gate[row*96 + c+1];
                }
            }
        }
    }
}

// ---------------- 4) conv1d+silu + proj (j-pair FFMA2) + dt + meta ----------------
// 32 tokens/block, 128 threads. xs stored DUPLICATED (v,v) as u64 so the proj
// x-operand is one LDS.64; weight j-pairs are contiguous floats (one LDS.64, no dup).
__global__ void k_cpd(const float* __restrict__ cw,
                      const float* __restrict__ Wx, const float* __restrict__ Wdt,
                      const float* __restrict__ bdt, const float* __restrict__ Dp){
    __shared__ __align__(16) u64   xsD[32*97];   // duplicated silu(conv) pairs
    __shared__ __align__(16) float Wxs[96*38];
    __shared__ __align__(16) float prs[32*10];   // dt_raw, pitch 10 (float2-aligned)
    __shared__ float cws[288];
    __shared__ float wdts[6*96];
    __shared__ float dps[96];
    __shared__ float bdts[96];
    int tid = threadIdx.x;                   // 128
    int tb  = blockIdx.x * 32;
    int tt0 = tb % NT;

    for (int idx=tid; idx<96*38; idx+=128) Wxs[idx] = Wx[idx];
    for (int idx=tid; idx<6*96;  idx+=128) wdts[idx] = Wdt[idx];
    if (tid < 96){
        cws[tid] = cw[tid*3+0]; cws[96+tid] = cw[tid*3+1]; cws[192+tid] = cw[tid*3+2];
        dps[tid] = Dp[tid]; bdts[tid] = bdt[tid];
    }
    __syncthreads();

    // conv + silu, store duplicated pair
    for (int idx=tid; idx<32*96; idx+=128){
        int l = idx/96, d = idx%96;
        int t = tt0 + l;
        const float* xp = g_xin + (tb + l)*96 + d;
        float v = xp[0]*cws[192+d];
        if (t >= 1) v = fmaf(xp[-96],  cws[96+d], v);
        if (t >= 2) v = fmaf(xp[-192], cws[d],    v);
        float s = silu_(v);
        xsD[l*97 + d] = pack2(s, s);
    }
    __syncthreads();

    // proj: [32 x 96] @ [96 x 38], j-pair packed FFMA2
    {
        int tp = tid & 15;                   // token pair 0..15
        int jpg = tid >> 4;                  // 0..7 ; jp = jpg + 8q, q<3, jp<19
        u64 acc[2][3] = {{0ull,0ull,0ull},{0ull,0ull,0ull}};
        const u64* x0 = &xsD[(2*tp)*97];
        const u64* x1 = x0 + 97;
        bool q2 = (jpg < 3);
        #pragma unroll 4
        for (int k=0;k<96;k++){
            u64 a0 = x0[k];
            u64 a1 = x1[k];
            const float* wr = &Wxs[k*38];
            u64 w0 = *reinterpret_cast<const u64*>(wr + 2*jpg);
            u64 w1 = *reinterpret_cast<const u64*>(wr + 2*jpg + 16);
            ffma2(acc[0][0], a0, w0);
            ffma2(acc[1][0], a1, w0);
            ffma2(acc[0][1], a0, w1);
            ffma2(acc[1][1], a1, w1);
            if (q2){
                u64 w2 = *reinterpret_cast<const u64*>(wr + 2*jpg + 32);
                ffma2(acc[0][2], a0, w2);
                ffma2(acc[1][2], a1, w2);
            }
        }
        #pragma unroll
        for (int t=0;t<2;t++){
            int tok = 2*tp + t;
            int row = tb + tok;
            #pragma unroll
            for (int q=0;q<3;q++){
                int jp = jpg + 8*q;
                if (jp < 19){
                    float2 v = unpack2(acc[t][q]);
                    int j = 2*jp;
                    if (j < 6){
                        prs[tok*10 + j]   = v.x;
                        prs[tok*10 + j+1] = v.y;
                    } else {
                        *reinterpret_cast<float2*>(&g_bc[row*32 + (j-6)]) = v;
                    }
                }
            }
        }
    }
    __syncthreads();

    // dt = softplus(dt_raw @ W_dt + b_dt) + meta pack
    const float* xsF = reinterpret_cast<const float*>(xsD);
    for (int idx=tid; idx<32*96; idx+=128){
        int l = idx/96, d = idx%96;
        float a = bdts[d];
        #pragma unroll
        for (int r=0;r<6;r++) a = fmaf(prs[l*10+r], wdts[r*96+d], a);
        float dt = softplus_(a);
        float xs = xsF[(l*97 + d)*2];
        float zg = g_zg[(tb+l)*96 + d];
        float4 m;
        m.x = dt;
        m.y = dt*xs;
        m.z = dps[d]*xs*zg;
        m.w = zg;
        g_meta[(tb+l)*96 + d] = m;
    }
}

// ---------------- 5) selective scan (proven R7): 8 lanes/d, 2 states/lane ----------------
__global__ void k_scan(const float* __restrict__ Alog){
    int b    = blockIdx.x / 6;
    int dgrp = blockIdx.x % 6;
    int w    = threadIdx.x >> 5;
    int lane = threadIdx.x & 31;
    int g    = lane >> 3;
    int sl   = lane & 7;
    int s0   = 2*sl;
    int d    = dgrp*16 + w*4 + g;

    float A0 = -__expf(Alog[d*DS + s0]);
    float A1 = -__expf(Alog[d*DS + s0 + 1]);
    float h0 = 0.f, h1 = 0.f;

    const float4* mp  = g_meta + b*NT*DI + d;
    const float*  bcp = g_bc   + b*NT*32;
    float*        yo  = g_yg   + b*NT*DI + d;

    #pragma unroll 4
    for (int t=0; t<NT; t++){
        float4 m = mp[t*DI];
        float2 Bv = *reinterpret_cast<const float2*>(bcp + t*32 + s0);
        float2 Cv = *reinterpret_cast<const float2*>(bcp + t*32 + 16 + s0);
        float e0 = __expf(m.x * A0);
        float e1 = __expf(m.x * A1);
        h0 = fmaf(e0, h0, m.y * Bv.x);
        h1 = fmaf(e1, h1, m.y * Bv.y);
        float yp = fmaf(h1, Cv.y, h0 * Cv.x);
        yp += __shfl_xor_sync(0xffffffffu, yp, 1);
        yp += __shfl_xor_sync(0xffffffffu, yp, 2);
        yp += __shfl_xor_sync(0xffffffffu, yp, 4);
        if (sl == 0){
            yo[t*DI] = fmaf(yp, m.w, m.z);
        }
    }
}

// ---------------- 6) heads: depthwise 3x3 + BN + silu + three matvecs ----------------
__global__ void k_final(const float* __restrict__ hd,
                        const float* __restrict__ bng, const float* __restrict__ bnb,
                        const float* __restrict__ bnm, const float* __restrict__ bnv,
                        const float* __restrict__ Wheat, const float* __restrict__ bheat,
                        const float* __restrict__ Woff,  const float* __restrict__ boff,
                        const float* __restrict__ Wsize, const float* __restrict__ bsize,
                        float* __restrict__ out){
    __shared__ float fr[3][HP][97];
    __shared__ float gs[HP][97];
    int tid = threadIdx.x;
    int b = blockIdx.x / HP;
    int h = blockIdx.x % HP;

    for (int idx=tid; idx<3*HP*96; idx+=128){
        int r = idx/(HP*96);
        int rem = idx - r*HP*96;
        int wq = rem/96, d = rem%96;
        int hh = h - 1 + r;
        fr[r][wq][d] = (hh>=0 && hh<HP) ? g_tokens[(b*NT + hh*HP + wq)*DM + d] : 0.f;
    }
    __syncthreads();

    for (int idx=tid; idx<HP*96; idx+=128){
        int wq = idx/96, d = idx%96;
        float a = 0.f;
        #pragma unroll
        for (int i=0;i<3;i++)
            #pragma unroll
            for (int j=0;j<3;j++){
                int ww = wq - 1 + j;
                if (ww>=0 && ww<HP) a = fmaf(fr[i][ww][d], hd[d*9 + i*3 + j], a);
            }
        a = (a - bnm[d]) * rsqrtf(bnv[d] + 1e-5f);
        gs[wq][d] = silu_(a*bng[d] + bnb[d]);
    }
    __syncthreads();

    const int HEAT_OFF = 0;
    const int OFF_OFF  = NB*5*NT;
    const int SIZE_OFF = OFF_OFF + NB*2*NT;
    for (int idx=tid; idx<HP*9; idx+=128){
        int wq = idx/9, o = idx%9;
        if (o < 5){
            float a = bheat[o];
            #pragma unroll 8
            for (int d=0; d<96; d++) a = fmaf(gs[wq][d], Wheat[o*96+d], a);
            out[HEAT_OFF + ((b*5+o)*HP + h)*HP + wq] = a;
        } else if (o < 7){
            int oo = o-5;
            float a = boff[oo];
            #pragma unroll 8
            for (int d=0; d<96; d++) a = fmaf(fr[1][wq][d], Woff[oo*96+d], a);
            out[OFF_OFF + ((b*2+oo)*HP + h)*HP + wq] = a;
        } else {
            int oo = o-7;
            float a = bsize[oo];
            #pragma unroll 8
            for (int d=0; d<96; d++) a = fmaf(fr[1][wq][d], Wsize[oo*96+d], a);
            out[SIZE_OFF + ((b*2+oo)*HP + h)*HP + wq] = a;
        }
    }
}

// ---------------- launch ----------------
extern "C" void kernel_launch(void* const* d_in, const int* in_sizes, int n_in,
                              void* d_out, int out_size){
    const float* x      = (const float*)d_in[0];
    const float* W_pe   = (const float*)d_in[1];
    const float* b_pe   = (const float*)d_in[2];
    const float* W_vis  = (const float*)d_in[3];
    const float* b_vis  = (const float*)d_in[4];
    const float* dn_g   = (const float*)d_in[5];
    const float* dn_b   = (const float*)d_in[6];
    const float* W_gate = (const float*)d_in[7];
    const float* b_gate = (const float*)d_in[8];
    const float* ln_g   = (const float*)d_in[9];
    const float* ln_b   = (const float*)d_in[10];
    const float* W_in   = (const float*)d_in[11];
    const float* conv_w = (const float*)d_in[12];
    const float* W_xprj = (const float*)d_in[13];
    const float* W_dt   = (const float*)d_in[14];
    const float* b_dt   = (const float*)d_in[15];
    const float* A_log  = (const float*)d_in[16];
    const float* Dp     = (const float*)d_in[17];
    const float* W_out  = (const float*)d_in[18];
    const float* hd_dw  = (const float*)d_in[19];
    const float* bn_g   = (const float*)d_in[20];
    const float* bn_b   = (const float*)d_in[21];
    const float* bn_m   = (const float*)d_in[22];
    const float* bn_v   = (const float*)d_in[23];
    const float* W_heat = (const float*)d_in[24];
    const float* b_heat = (const float*)d_in[25];
    const float* W_off  = (const float*)d_in[26];
    const float* b_off  = (const float*)d_in[27];
    const float* W_size = (const float*)d_in[28];
    const float* b_size = (const float*)d_in[29];
    float* out = (float*)d_out;

    k_wt<<<(768*96+255)/256, 256>>>(W_pe);
    k_blur<<<192*144, 256>>>(x);
    k_patch<<<NR/64, 128>>>(b_pe);

    k_rowgemm<0><<<NR/64, 128>>>(W_gate, 96, dn_g, dn_b, W_vis, b_vis, b_gate);

    for (int rep=0; rep<4; rep++){
        k_rowgemm<1><<<NR/64, 128>>>(W_in, 192, ln_g, ln_b, nullptr, nullptr, nullptr);
        k_cpd<<<NR/32, 128>>>(conv_w, W_xprj, W_dt, b_dt, Dp);
        k_scan<<<NB*6, 128>>>(A_log);
        k_rowgemm<2><<<NR/64, 128>>>(W_out, 96, nullptr, nullptr, nullptr, nullptr, nullptr);
    }

    k_final<<<NB*HP, 128>>>(hd_dw, bn_g, bn_b, bn_m, bn_v,
                            W_heat, b_heat, W_off, b_off, W_size, b_size, out);
}

// round 10
// speedup vs baseline: 1.2689x; 1.1026x over previous
#include <cuda_runtime.h>
#include <math.h>

#define NB   64
#define IMG  384
#define CIN  3
#define PS   16
#define DM   96
#define DS   16
#define DI   96
#define HP   24
#define NT   576
#define NR   (NB*NT)          // 36864 token rows
#define NPIX (NB*CIN*IMG*IMG) // 28311552

// ---------------- scratch (device globals; no allocs allowed) ----------------
static __device__ float  g_xl[NPIX];        // preprocessed image, PATCH-MAJOR [gp][768]
static __device__ float  g_WpeT[768*96];    // transposed patch weights [k][d]
static __device__ float  g_tokens[NR*DM];
static __device__ float  g_vis[NR];
static __device__ float  g_gate[NR*DM];
static __device__ float  g_xin[NR*DI];      // pre-conv x branch
static __device__ float  g_zg[NR*DI];       // silu(z)*vis
static __device__ float  g_bc[NR*32];       // B(16) | C(16)
static __device__ float2 g_meta[NR*DI];     // {dt, xs}
static __device__ float  g_yg[NR*DI];       // y_raw = yp + D*xs  (zg applied in rg2)

__device__ __forceinline__ float sigm_(float x){ return 1.f/(1.f+__expf(-x)); }
__device__ __forceinline__ float silu_(float x){ return x/(1.f+__expf(-x)); }
__device__ __forceinline__ float softplus_(float x){ return (x>20.f)? x : __logf(1.f+__expf(x)); }

// ---- packed fp32x2 helpers (Blackwell FFMA2 path, PTX-only) ----
typedef unsigned long long u64;
__device__ __forceinline__ void ffma2(u64 &d, u64 a, u64 b){
    asm("fma.rn.f32x2 %0, %1, %2, %3;" : "=l"(d) : "l"(a), "l"(b), "l"(d));
}
__device__ __forceinline__ u64 pack2(float x, float y){
    u64 r;
    asm("mov.b64 %0, {%1, %2};" : "=l"(r) : "r"(__float_as_uint(x)), "r"(__float_as_uint(y)));
    return r;
}
__device__ __forceinline__ float2 unpack2(u64 v){
    unsigned lo, hi;
    asm("mov.b64 {%0, %1}, %2;" : "=r"(lo), "=r"(hi) : "l"(v));
    return make_float2(__uint_as_float(lo), __uint_as_float(hi));
}

// ---------------- 0) transpose W_pe once ----------------
__global__ void k_wt(const float* __restrict__ Wpe){
    int idx = blockIdx.x*blockDim.x + threadIdx.x;
    if (idx < 768*96){
        int k = idx/96, d = idx%96;
        g_WpeT[idx] = Wpe[d*768 + k];
    }
}

// ---------------- 1) fused 5x5 box blur + log contrast (smem tiles) ----------------
__global__ void k_blur(const float* __restrict__ x){
    __shared__ float in_s[36][37];
    __shared__ float hs[36][33];
    int tid = threadIdx.x;                   // 256
    int p = blockIdx.x / 144;                // plane = b*3 + c
    int t = blockIdx.x % 144;
    int y0 = (t/12)*32, x0 = (t%12)*32;
    const float* xp = x + (size_t)p*IMG*IMG;

    for (int idx=tid; idx<36*36; idx+=256){
        int r = idx/36, cc = idx%36;
        int yy = y0-2+r, xx = x0-2+cc;
        in_s[r][cc] = (yy>=0 && yy<IMG && xx>=0 && xx<IMG) ? xp[yy*IMG+xx] : 0.f;
    }
    __syncthreads();
    for (int idx=tid; idx<36*32; idx+=256){
        int r = idx/32, j = idx%32;
        hs[r][j] = in_s[r][j]+in_s[r][j+1]+in_s[r][j+2]+in_s[r][j+3]+in_s[r][j+4];
    }
    __syncthreads();
    int b = p/3, c = p%3;
    for (int idx=tid; idx<32*32; idx+=256){
        int r = idx/32, j = idx%32;
        float bl = (hs[r][j]+hs[r+1][j]+hs[r+2][j]+hs[r+3][j]+hs[r+4][j])*(1.f/25.f);
        float xv = in_s[r+2][j+2];
        float v  = __logf(1.f + fmaxf(xv,0.f)) - __logf(1.f + fmaxf(bl,0.f));
        int yy = y0+r, xx = x0+j;
        int gp  = b*NT + (yy>>4)*HP + (xx>>4);
        int col = c*256 + (yy&15)*16 + (xx&15);
        g_xl[gp*768 + col] = v;
    }
}

// ---------------- 2) patch embed GEMM, 32-row blocks: [36864 x 768] @ [768 x 96] ----------------
__global__ void k_patch(const float* __restrict__ bpe){
    __shared__ __align__(16) float As[32][64];
    __shared__ __align__(16) float Bs[64][96];
    int tid = threadIdx.x;                   // 128
    int tx = tid & 15, ty = tid >> 4;        // tx 0..15 (3 u64 cols), ty 0..7
    int rowbase = blockIdx.x * 32;
    int tx6 = tx*6;

    u64 acc[4][3];
    #pragma unroll
    for (int i=0;i<4;i++){ acc[i][0]=0ull; acc[i][1]=0ull; acc[i][2]=0ull; }

    const float4* Xg = reinterpret_cast<const float4*>(g_xl);
    const float4* Wg = reinterpret_cast<const float4*>(g_WpeT);
    float4* As4 = reinterpret_cast<float4*>(&As[0][0]);
    float4* Bs4 = reinterpret_cast<float4*>(&Bs[0][0]);

    for (int kc=0; kc<12; kc++){
        #pragma unroll
        for (int r=0;r<4;r++){
            int idx = tid + 128*r;           // < 512
            int row = idx >> 4, c4 = idx & 15;
            As4[idx] = Xg[(rowbase+row)*192 + kc*16 + c4];
        }
        #pragma unroll
        for (int r=0;r<12;r++){
            int idx = tid + 128*r;           // < 1536
            int kk = idx/24, c4 = idx%24;
            Bs4[idx] = Wg[(kc*64+kk)*24 + c4];
        }
        __syncthreads();
        #pragma unroll 8
        for (int kk=0;kk<64;kk++){
            const u64* bp = reinterpret_cast<const u64*>(&Bs[kk][tx6]);
            u64 b0 = bp[0], b1 = bp[1], b2 = bp[2];
            #pragma unroll
            for (int i=0;i<4;i++){
                float a = As[ty + 8*i][kk];
                u64 ap = pack2(a, a);
                ffma2(acc[i][0], ap, b0);
                ffma2(acc[i][1], ap, b1);
                ffma2(acc[i][2], ap, b2);
            }
        }
        __syncthreads();
    }
    #pragma unroll
    for (int i=0;i<4;i++){
        int row = rowbase + ty + 8*i;
        #pragma unroll
        for (int j=0;j<3;j++){
            float2 v = unpack2(acc[i][j]);
            int c = tx6 + 2*j;
            g_tokens[row*DM + c]   = v.x + bpe[c];
            g_tokens[row*DM + c+1] = v.y + bpe[c+1];
        }
    }
}

// ---------------- 3) row GEMM, 32-row blocks, fused LN + epilogues ----------------
// MODE 0: raw tokens -> vis ; LN(dn) written back ; gate = sigmoid(LN @ W_gate + b)
// MODE 1: LN(ln)(tokens) @ W_in ; both halves (cb=0 -> g_xin, cb=96 -> g_zg = silu(z)*vis)
// MODE 2: (g_yg * g_zg) @ W_out ; tokens += out * gate
template<int MODE>
__global__ void k_rowgemm(const float* __restrict__ W, int wstride,
                          const float* __restrict__ lng, const float* __restrict__ lnb,
                          const float* __restrict__ Wvis, const float* __restrict__ bvis,
                          const float* __restrict__ bgate){
    __shared__ __align__(16) float As[32][96];
    __shared__ __align__(16) float Bs[32][96];
    int tid = threadIdx.x;                   // 128
    int tx = tid & 15, ty = tid >> 4;
    int rowbase = blockIdx.x * 32;
    int tx6 = tx*6;

    float4* As4 = reinterpret_cast<float4*>(&As[0][0]);
    float4* Bs4 = reinterpret_cast<float4*>(&Bs[0][0]);
    if (MODE == 2){
        const float4* Yg = reinterpret_cast<const float4*>(g_yg + rowbase*96);
        const float4* Zg = reinterpret_cast<const float4*>(g_zg + rowbase*96);
        #pragma unroll
        for (int r=0;r<6;r++){
            int idx = tid + 128*r;           // < 768
            float4 a = Yg[idx];
            float4 z = Zg[idx];
            a.x*=z.x; a.y*=z.y; a.z*=z.z; a.w*=z.w;
            As4[idx] = a;
        }
    } else {
        const float4* Ag = reinterpret_cast<const float4*>(g_tokens + rowbase*96);
        #pragma unroll
        for (int r=0;r<6;r++) As4[tid + 128*r] = Ag[tid + 128*r];
    }
    __syncthreads();

    if (MODE != 2){
        int warp = tid >> 5, lane = tid & 31;
        for (int rr=0; rr<8; rr++){
            int row = warp*8 + rr;
            float v0 = As[row][lane], v1 = As[row][lane+32], v2 = As[row][lane+64];
            float s = v0+v1+v2;
            #pragma unroll
            for (int o=16;o;o>>=1) s += __shfl_xor_sync(0xffffffffu, s, o);
            float m = s*(1.f/96.f);
            float d0=v0-m, d1=v1-m, d2=v2-m;
            float q = d0*d0 + d1*d1 + d2*d2;
            #pragma unroll
            for (int o=16;o;o>>=1) q += __shfl_xor_sync(0xffffffffu, q, o);
            float rs = rsqrtf(q*(1.f/96.f) + 1e-5f);
            if (MODE == 0){
                float vd = v0*Wvis[lane] + v1*Wvis[lane+32] + v2*Wvis[lane+64];
                #pragma unroll
                for (int o=16;o;o>>=1) vd += __shfl_xor_sync(0xffffffffu, vd, o);
                if (lane==0) g_vis[rowbase+row] = sigm_(vd + bvis[0]);
            }
            float n0 = d0*rs*lng[lane]    + lnb[lane];
            float n1 = d1*rs*lng[lane+32] + lnb[lane+32];
            float n2 = d2*rs*lng[lane+64] + lnb[lane+64];
            As[row][lane]=n0; As[row][lane+32]=n1; As[row][lane+64]=n2;
            if (MODE == 0){
                float* tp = g_tokens + (rowbase+row)*96;
                tp[lane]=n0; tp[lane+32]=n1; tp[lane+64]=n2;
            }
        }
    }

    const int NHALF = (MODE==1) ? 2 : 1;
    for (int half=0; half<NHALF; half++){
        int cb = half*96;

        u64 acc[4][3];
        #pragma unroll
        for (int i=0;i<4;i++){ acc[i][0]=0ull; acc[i][1]=0ull; acc[i][2]=0ull; }

        for (int kc=0;kc<3;kc++){
            __syncthreads();
            #pragma unroll
            for (int r=0;r<6;r++){
                int idx = tid + 128*r;        // < 768
                int kk = idx/24, c4 = idx%24;
                Bs4[idx] = *reinterpret_cast<const float4*>(W + (kc*32+kk)*wstride + cb + c4*4);
            }
            __syncthreads();
            #pragma unroll 8
            for (int kk=0;kk<32;kk++){
                const u64* bp = reinterpret_cast<const u64*>(&Bs[kk][tx6]);
                u64 b0 = bp[0], b1 = bp[1], b2 = bp[2];
                int kidx = kc*32 + kk;
                #pragma unroll
                for (int i=0;i<4;i++){
                    float a = As[ty + 8*i][kidx];
                    u64 ap = pack2(a, a);
                    ffma2(acc[i][0], ap, b0);
                    ffma2(acc[i][1], ap, b1);
                    ffma2(acc[i][2], ap, b2);
                }
            }
        }

        #pragma unroll
        for (int i=0;i<4;i++){
            int row = rowbase + ty + 8*i;
            float visr = 0.f;
            if (MODE == 1 && half == 1) visr = g_vis[row];
            #pragma unroll
            for (int j=0;j<3;j++){
                float2 v = unpack2(acc[i][j]);
                int c = tx6 + 2*j;
                if (MODE == 0){
                    g_gate[row*96 + c]   = sigm_(v.x + bgate[c]);
                    g_gate[row*96 + c+1] = sigm_(v.y + bgate[c+1]);
                } else if (MODE == 1){
                    if (half == 0){
                        g_xin[row*96 + c]   = v.x;
                        g_xin[row*96 + c+1] = v.y;
                    } else {
                        g_zg[row*96 + c]   = silu_(v.x)*visr;
                        g_zg[row*96 + c+1] = silu_(v.y)*visr;
                    }
                } else {
                    g_tokens[row*96 + c]   += v.x * g_gate[row*96 + c];
                    g_tokens[row*96 + c+1] += v.y * g_gate[row*96 + c+1];
                }
            }
        }
    }
}

// ---------------- 4) conv1d+silu + proj (j-pair FFMA2) + dt + meta2 ----------------
__global__ void k_cpd(const float* __restrict__ cw,
                      const float* __restrict__ Wx, const float* __restrict__ Wdt,
                      const float* __restrict__ bdt){
    __shared__ __align__(16) u64   xsD[32*97];   // duplicated silu(conv) pairs
    __shared__ __align__(16) float Wxs[96*38];
    __shared__ __align__(16) float prs[32*10];   // dt_raw, pitch 10
    __shared__ float cws[288];
    __shared__ float wdts[6*96];
    __shared__ float bdts[96];
    int tid = threadIdx.x;                   // 128
    int tb  = blockIdx.x * 32;
    int tt0 = tb % NT;

    for (int idx=tid; idx<96*38; idx+=128) Wxs[idx] = Wx[idx];
    for (int idx=tid; idx<6*96;  idx+=128) wdts[idx] = Wdt[idx];
    if (tid < 96){
        cws[tid] = cw[tid*3+0]; cws[96+tid] = cw[tid*3+1]; cws[192+tid] = cw[tid*3+2];
        bdts[tid] = bdt[tid];
    }
    __syncthreads();

    // conv + silu, store duplicated pair
    for (int idx=tid; idx<32*96; idx+=128){
        int l = idx/96, d = idx%96;
        int t = tt0 + l;
        const float* xp = g_xin + (tb + l)*96 + d;
        float v = xp[0]*cws[192+d];
        if (t >= 1) v = fmaf(xp[-96],  cws[96+d], v);
        if (t >= 2) v = fmaf(xp[-192], cws[d],    v);
        float s = silu_(v);
        xsD[l*97 + d] = pack2(s, s);
    }
    __syncthreads();

    // proj: [32 x 96] @ [96 x 38], j-pair packed FFMA2
    {
        int tp = tid & 15;
        int jpg = tid >> 4;                  // 0..7
        u64 acc[2][3] = {{0ull,0ull,0ull},{0ull,0ull,0ull}};
        const u64* x0 = &xsD[(2*tp)*97];
        const u64* x1 = x0 + 97;
        bool q2 = (jpg < 3);
        #pragma unroll 4
        for (int k=0;k<96;k++){
            u64 a0 = x0[k];
            u64 a1 = x1[k];
            const float* wr = &Wxs[k*38];
            u64 w0 = *reinterpret_cast<const u64*>(wr + 2*jpg);
            u64 w1 = *reinterpret_cast<const u64*>(wr + 2*jpg + 16);
            ffma2(acc[0][0], a0, w0);
            ffma2(acc[1][0], a1, w0);
            ffma2(acc[0][1], a0, w1);
            ffma2(acc[1][1], a1, w1);
            if (q2){
                u64 w2 = *reinterpret_cast<const u64*>(wr + 2*jpg + 32);
                ffma2(acc[0][2], a0, w2);
                ffma2(acc[1][2], a1, w2);
            }
        }
        #pragma unroll
        for (int t=0;t<2;t++){
            int tok = 2*tp + t;
            int row = tb + tok;
            #pragma unroll
            for (int q=0;q<3;q++){
                int jp = jpg + 8*q;
                if (jp < 19){
                    float2 v = unpack2(acc[t][q]);
                    int j = 2*jp;
                    if (j < 6){
                        prs[tok*10 + j]   = v.x;
                        prs[tok*10 + j+1] = v.y;
                    } else {
                        *reinterpret_cast<float2*>(&g_bc[row*32 + (j-6)]) = v;
                    }
                }
            }
        }
    }
    __syncthreads();

    // dt = softplus(dt_raw @ W_dt + b_dt), meta2 = {dt, xs}
    const float* xsF = reinterpret_cast<const float*>(xsD);
    for (int idx=tid; idx<32*96; idx+=128){
        int l = idx/96, d = idx%96;
        float a = bdts[d];
        #pragma unroll
        for (int r=0;r<6;r++) a = fmaf(prs[l*10+r], wdts[r*96+d], a);
        float dt = softplus_(a);
        float xs = xsF[(l*97 + d)*2];
        g_meta[(tb+l)*96 + d] = make_float2(dt, xs);
    }
}

// ---------------- 5) selective scan: 8 lanes/d, 2 states/lane ----------------
__global__ void k_scan(const float* __restrict__ Alog, const float* __restrict__ Dp){
    int b    = blockIdx.x / 6;
    int dgrp = blockIdx.x % 6;
    int w    = threadIdx.x >> 5;
    int lane = threadIdx.x & 31;
    int g    = lane >> 3;
    int sl   = lane & 7;
    int s0   = 2*sl;
    int d    = dgrp*16 + w*4 + g;

    float A0 = -__expf(Alog[d*DS + s0]);
    float A1 = -__expf(Alog[d*DS + s0 + 1]);
    float Dd = Dp[d];
    float h0 = 0.f, h1 = 0.f;

    const float2* mp  = g_meta + b*NT*DI + d;
    const float*  bcp = g_bc   + b*NT*32;
    float*        yo  = g_yg   + b*NT*DI + d;

    #pragma unroll 4
    for (int t=0; t<NT; t++){
        float2 m = mp[t*DI];
        float2 Bv = *reinterpret_cast<const float2*>(bcp + t*32 + s0);
        float2 Cv = *reinterpret_cast<const float2*>(bcp + t*32 + 16 + s0);
        float u = m.x * m.y;
        float e0 = __expf(m.x * A0);
        float e1 = __expf(m.x * A1);
        h0 = fmaf(e0, h0, u * Bv.x);
        h1 = fmaf(e1, h1, u * Bv.y);
        float yp = fmaf(h1, Cv.y, h0 * Cv.x);
        yp += __shfl_xor_sync(0xffffffffu, yp, 1);
        yp += __shfl_xor_sync(0xffffffffu, yp, 2);
        yp += __shfl_xor_sync(0xffffffffu, yp, 4);
        if (sl == 0){
            yo[t*DI] = fmaf(Dd, m.y, yp);
        }
    }
}

// ---------------- 6) heads: depthwise 3x3 + BN + silu + three matvecs ----------------
__global__ void k_final(const float* __restrict__ hd,
                        const float* __restrict__ bng, const float* __restrict__ bnb,
                        const float* __restrict__ bnm, const float* __restrict__ bnv,
                        const float* __restrict__ Wheat, const float* __restrict__ bheat,
                        const float* __restrict__ Woff,  const float* __restrict__ boff,
                        const float* __restrict__ Wsize, const float* __restrict__ bsize,
                        float* __restrict__ out){
    __shared__ float fr[3][HP][97];
    __shared__ float gs[HP][97];
    int tid = threadIdx.x;
    int b = blockIdx.x / HP;
    int h = blockIdx.x % HP;

    for (int idx=tid; idx<3*HP*96; idx+=128){
        int r = idx/(HP*96);
        int rem = idx - r*HP*96;
        int wq = rem/96, d = rem%96;
        int hh = h - 1 + r;
        fr[r][wq][d] = (hh>=0 && hh<HP) ? g_tokens[(b*NT + hh*HP + wq)*DM + d] : 0.f;
    }
    __syncthreads();

    for (int idx=tid; idx<HP*96; idx+=128){
        int wq = idx/96, d = idx%96;
        float a = 0.f;
        #pragma unroll
        for (int i=0;i<3;i++)
            #pragma unroll
            for (int j=0;j<3;j++){
                int ww = wq - 1 + j;
                if (ww>=0 && ww<HP) a = fmaf(fr[i][ww][d], hd[d*9 + i*3 + j], a);
            }
        a = (a - bnm[d]) * rsqrtf(bnv[d] + 1e-5f);
        gs[wq][d] = silu_(a*bng[d] + bnb[d]);
    }
    __syncthreads();

    const int HEAT_OFF = 0;
    const int OFF_OFF  = NB*5*NT;
    const int SIZE_OFF = OFF_OFF + NB*2*NT;
    for (int idx=tid; idx<HP*9; idx+=128){
        int wq = idx/9, o = idx%9;
        if (o < 5){
            float a = bheat[o];
            #pragma unroll 8
            for (int d=0; d<96; d++) a = fmaf(gs[wq][d], Wheat[o*96+d], a);
            out[HEAT_OFF + ((b*5+o)*HP + h)*HP + wq] = a;
        } else if (o < 7){
            int oo = o-5;
            float a = boff[oo];
            #pragma unroll 8
            for (int d=0; d<96; d++) a = fmaf(fr[1][wq][d], Woff[oo*96+d], a);
            out[OFF_OFF + ((b*2+oo)*HP + h)*HP + wq] = a;
        } else {
            int oo = o-7;
            float a = bsize[oo];
            #pragma unroll 8
            for (int d=0; d<96; d++) a = fmaf(fr[1][wq][d], Wsize[oo*96+d], a);
            out[SIZE_OFF + ((b*2+oo)*HP + h)*HP + wq] = a;
        }
    }
}

// ---------------- launch ----------------
extern "C" void kernel_launch(void* const* d_in, const int* in_sizes, int n_in,
                              void* d_out, int out_size){
    const float* x      = (const float*)d_in[0];
    const float* W_pe   = (const float*)d_in[1];
    const float* b_pe   = (const float*)d_in[2];
    const float* W_vis  = (const float*)d_in[3];
    const float* b_vis  = (const float*)d_in[4];
    const float* dn_g   = (const float*)d_in[5];
    const float* dn_b   = (const float*)d_in[6];
    const float* W_gate = (const float*)d_in[7];
    const float* b_gate = (const float*)d_in[8];
    const float* ln_g   = (const float*)d_in[9];
    const float* ln_b   = (const float*)d_in[10];
    const float* W_in   = (const float*)d_in[11];
    const float* conv_w = (const float*)d_in[12];
    const float* W_xprj = (const float*)d_in[13];
    const float* W_dt   = (const float*)d_in[14];
    const float* b_dt   = (const float*)d_in[15];
    const float* A_log  = (const float*)d_in[16];
    const float* Dp     = (const float*)d_in[17];
    const float* W_out  = (const float*)d_in[18];
    const float* hd_dw  = (const float*)d_in[19];
    const float* bn_g   = (const float*)d_in[20];
    const float* bn_b   = (const float*)d_in[21];
    const float* bn_m   = (const float*)d_in[22];
    const float* bn_v   = (const float*)d_in[23];
    const float* W_heat = (const float*)d_in[24];
    const float* b_heat = (const float*)d_in[25];
    const float* W_off  = (const float*)d_in[26];
    const float* b_off  = (const float*)d_in[27];
    const float* W_size = (const float*)d_in[28];
    const float* b_size = (const float*)d_in[29];
    float* out = (float*)d_out;

    k_wt<<<(768*96+255)/256, 256>>>(W_pe);
    k_blur<<<192*144, 256>>>(x);
    k_patch<<<NR/32, 128>>>(b_pe);

    k_rowgemm<0><<<NR/32, 128>>>(W_gate, 96, dn_g, dn_b, W_vis, b_vis, b_gate);

    for (int rep=0; rep<4; rep++){
        k_rowgemm<1><<<NR/32, 128>>>(W_in, 192, ln_g, ln_b, nullptr, nullptr, nullptr);
        k_cpd<<<NR/32, 128>>>(conv_w, W_xprj, W_dt, b_dt);
        k_scan<<<NB*6, 128>>>(A_log, Dp);
        k_rowgemm<2><<<NR/32, 128>>>(W_out, 96, nullptr, nullptr, nullptr, nullptr, nullptr);
    }

    k_final<<<NB*HP, 128>>>(hd_dw, bn_g, bn_b, bn_m, bn_v,
                            W_heat, b_heat, W_off, b_off, W_size, b_size, out);
}